// round 10
// baseline (speedup 1.0000x reference)
#include <cuda_runtime.h>
#include <math.h>

// Shapes (hardcoded from reference): B=16, N=32, C=8, O=16
// d_in order: x0, x1, x2, x3, W0, b0, W1, b1, W2, b2, W3, b3
// d_out: concat(out0[16,16], out1[16,32,16], out2[16,32,32,16], out3[16,32,32,32,16])

#define NB 16
#define NN 32

// Scratch (device global — no runtime allocation)
__device__ float g_R3[NB * NN * NN * 16];   // reduce(x3): [b,a1,a2][max8|min8]

__device__ __forceinline__ float sigm(float x) {
    return __fdividef(1.0f, 1.0f + __expf(-x));
}

// Packed fp32x2 helpers (sm_100+). Per-lane rounding identical to scalar FFMA.
#define FFMA2(ACC, S, W) \
    asm("fma.rn.f32x2 %0, %1, %2, %0;" : "+l"(ACC) : "l"(S), "l"(W))
#define ADD2(D, A, B) \
    asm("add.rn.f32x2 %0, %1, %2;" : "=l"(D) : "l"(A), "l"(B))
#define PACK2(D, F) \
    asm("mov.b64 %0, {%1, %1};" : "=l"(D) : "r"(__float_as_uint(F)))
#define UNPACK2(LO, HI, A) \
    asm("mov.b64 {%0, %1}, %2;" : "=r"(LO), "=r"(HI) : "l"(A))

// ---------------------------------------------------------------------------
// Main: out3 + R3. grid = B*N = 512 CTAs (b,i), 512 threads, 175.6KB dyn smem.
// Thread: half=tid>>8 (channel half, o0=half*8), idx=tid&255, k=idx&31,
//         jq=idx>>5; positions j = jq*4 + {0..3}  (G=4, 8 channels each).
// Weight u64s (4 per (term,cc)) are reused across 4 positions -> half the
// broadcast weight-LDS of the R9 version.
// ---------------------------------------------------------------------------
#define PITCH 260
#define SLICE (32 * PITCH)              // 8320
#define SM_S1 0
#define SM_S2 SLICE
#define SM_S3 (2 * SLICE)
#define SM_X2  (3 * SLICE)              // +8192
#define SM_X2T (3 * SLICE + 8192)       // +8192
#define SM_W   (3 * SLICE + 16384)      // +1536
#define SM_A   (3 * SLICE + 17920)      // +512
#define SM_C   (3 * SLICE + 18432)      // +512
#define SM_FLOATS (3 * SLICE + 18944)   // 43904 floats = 175616 bytes

__global__ void __launch_bounds__(512) k_main(
    const float* __restrict__ x2, const float* __restrict__ x3,
    const float* __restrict__ W3, const float* __restrict__ b3,
    float* __restrict__ out3)
{
    extern __shared__ __align__(16) float sm[];
    int blk = blockIdx.x;
    int b = blk >> 5;
    int i = blk & 31;
    int tid = threadIdx.x;

    const float* x3b = x3 + (size_t)b * 32 * 32 * 32 * 8;
    const float* x2b = x2 + (size_t)b * 8192;

    // ---- stage (coalesced float4 global reads) ----
    {
        const float4* src = (const float4*)(x3b + i * 8192);
        for (int idx = tid; idx < 2048; idx += 512) {
            int r = idx >> 6, w = idx & 63;
            *(float4*)(sm + SM_S1 + r * PITCH + w * 4) = src[idx];
        }
    }
    for (int idx = tid; idx < 2048; idx += 512) {
        int a = idx >> 6, w = idx & 63;
        float4 v = *(const float4*)(x3b + a * 8192 + i * 256 + w * 4);
        *(float4*)(sm + SM_S2 + a * PITCH + w * 4) = v;
    }
    for (int idx = tid; idx < 2048; idx += 512) {
        int ch = idx >> 1, hf = idx & 1;
        int a1 = ch >> 5, a2 = ch & 31;
        float4 v = *(const float4*)(x3b + a1 * 8192 + a2 * 256 + i * 8 + hf * 4);
        *(float4*)(sm + SM_S3 + a1 * PITCH + a2 * 8 + hf * 4) = v;
    }
    for (int idx = tid; idx < 2048; idx += 512) {
        float4 v = *(const float4*)(x2b + idx * 4);
        *(float4*)(sm + SM_X2 + idx * 4) = v;
        int hf = idx & 1, kk = (idx >> 1) & 31, jj = idx >> 6;
        *(float4*)(sm + SM_X2T + (kk * 32 + jj) * 8 + hf * 4) = v;
    }
    if (tid < 384) {
        ((float4*)(sm + SM_W))[tid] = ((const float4*)W3)[tid];
    }
    __syncthreads();

    // ---- sA[j][o] (incl b3), sC[k][o] ----
    {
        int j = tid >> 4, o = tid & 15;
        float accA = b3[o], accC = 0.0f;
        #pragma unroll
        for (int cc = 0; cc < 8; cc++) {
            float xij = sm[SM_X2 + (i * 32 + j) * 8 + cc];
            float xji = sm[SM_X2 + (j * 32 + i) * 8 + cc];
            accA += xij * sm[SM_W + cc * 16 + o] + xji * sm[SM_W + (32 + cc) * 16 + o];
            accC += xij * sm[SM_W + (16 + cc) * 16 + o] + xji * sm[SM_W + (48 + cc) * 16 + o];
        }
        sm[SM_A + tid] = accA;
        sm[SM_C + tid] = accC;
    }
    __syncthreads();

    // ---- R3[b,i,j,:] from s1 (masked reduce over a3, exclude a3==j) ----
    if (tid < 256) {
        int j = tid >> 3, c = tid & 7;
        const float* row = sm + SM_S1 + j * PITCH + c;
        float vmax = -INFINITY, vmin = INFINITY;
        #pragma unroll
        for (int a = 0; a < 32; a++) {
            float v = row[a * 8];
            float vm = (a == j) ? 0.0f : v;
            float vn = (a == j) ? 1.0f : v;
            vmax = fmaxf(vmax, vm);
            vmin = fminf(vmin, vn);
        }
        int o = ((b * 32 + i) * 32 + j) * 16;
        g_R3[o + c] = vmax;
        g_R3[o + 8 + c] = vmin;
    }

    // ---- main compute: 4 positions x 8 channels, packed f32x2 ----
    int half = tid >> 8;          // 0/1 -> channels o0..o0+7
    int o0 = half * 8;
    int idx = tid & 255;
    int k = idx & 31;
    int jq = idx >> 5;            // 0..7 -> j = jq*4 + g

    unsigned long long acc[4][4];
    int rowoff[4], coloff[4], x2off[4];
    #pragma unroll
    for (int g = 0; g < 4; g++) {
        int j = jq * 4 + g;
        const unsigned long long* pa = (const unsigned long long*)(sm + SM_A + j * 16 + o0);
        const unsigned long long* pc = (const unsigned long long*)(sm + SM_C + k * 16 + o0);
        #pragma unroll
        for (int q = 0; q < 4; q++) {
            unsigned long long t;
            ADD2(t, pa[q], pc[q]);
            acc[g][q] = t;
        }
        rowoff[g] = j * PITCH + k * 8;
        coloff[g] = k * PITCH + j * 8;
        x2off[g]  = (j * 32 + k) * 8;
    }

    const int RB[8] = {8, 24, 40, 56, 72, 88, 64, 80};  // W3 row blocks per term

    #pragma unroll
    for (int t = 0; t < 8; t++) {
        float v[4][8];
        #pragma unroll
        for (int g = 0; g < 4; g++) {
            const float* p;
            if (t < 6) {
                const float* sl = sm + (t >> 1) * SLICE;
                p = sl + ((t & 1) ? coloff[g] : rowoff[g]);
            } else if (t == 6) {
                p = sm + SM_X2 + x2off[g];      // x2[b,j,k]
            } else {
                p = sm + SM_X2T + x2off[g];     // x2[b,k,j]
            }
            float4 lo = *(const float4*)p;
            float4 hi = *(const float4*)(p + 4);
            v[g][0] = lo.x; v[g][1] = lo.y; v[g][2] = lo.z; v[g][3] = lo.w;
            v[g][4] = hi.x; v[g][5] = hi.y; v[g][6] = hi.z; v[g][7] = hi.w;
        }
        const float* wrow = sm + SM_W + RB[t] * 16 + o0;
        #pragma unroll
        for (int cc = 0; cc < 8; cc++) {
            const unsigned long long* w4 = (const unsigned long long*)(wrow + cc * 16);
            unsigned long long w0 = w4[0], w1 = w4[1], w2 = w4[2], w3 = w4[3];
            #pragma unroll
            for (int g = 0; g < 4; g++) {
                unsigned long long s2p;
                PACK2(s2p, v[g][cc]);
                FFMA2(acc[g][0], s2p, w0);
                FFMA2(acc[g][1], s2p, w1);
                FFMA2(acc[g][2], s2p, w2);
                FFMA2(acc[g][3], s2p, w3);
            }
        }
    }

    // ---- sigmoid + store (8 channels per position) ----
    #pragma unroll
    for (int g = 0; g < 4; g++) {
        int j = jq * 4 + g;
        float r[8];
        #pragma unroll
        for (int q = 0; q < 4; q++) {
            unsigned int lo, hi;
            UNPACK2(lo, hi, acc[g][q]);
            r[q * 2 + 0] = sigm(__uint_as_float(lo));
            r[q * 2 + 1] = sigm(__uint_as_float(hi));
        }
        float* dst = out3 + ((((size_t)b * 32 + i) * 32 + j) * 32 + k) * 16 + o0;
        *(float4*)dst = make_float4(r[0], r[1], r[2], r[3]);
        *(float4*)(dst + 4) = make_float4(r[4], r[5], r[6], r[7]);
    }
}

// ---------------------------------------------------------------------------
// Tail A: out2 — 2 threads per (b,i,j), 8 outputs each. grid 128.
// ---------------------------------------------------------------------------
__global__ void __launch_bounds__(256) k_tail2(
    const float* __restrict__ x1, const float* __restrict__ x2,
    const float* __restrict__ W2, const float* __restrict__ b2,
    float* __restrict__ out2)
{
    int blk = blockIdx.x, tid = threadIdx.x;
    __shared__ __align__(16) float sW2[64 * 16];
    for (int idx = tid; idx < 1024; idx += 256) sW2[idx] = W2[idx];
    __syncthreads();

    int idx = blk * 256 + tid;
    int half = idx & 1;
    int pos = idx >> 1;                 // b,i,j
    int j = pos & 31, i = (pos >> 5) & 31, b = pos >> 10;
    int o0 = half * 8;

    float acc[8];
    {
        const float* bb = b2 + o0;
        #pragma unroll
        for (int o = 0; o < 8; o++) acc[o] = bb[o];
    }

    #define ACC_SRC(PTR, RB_, CNT)                                         \
        {                                                                  \
            const float* _s = (PTR);                                       \
            _Pragma("unroll")                                              \
            for (int c = 0; c < (CNT); c++) {                              \
                float v = _s[c];                                           \
                const float* w = sW2 + ((RB_) + c) * 16 + o0;              \
                _Pragma("unroll")                                          \
                for (int o = 0; o < 8; o++) acc[o] += v * w[o];            \
            }                                                              \
        }

    ACC_SRC(x1 + (b * 32 + i) * 8, 0, 8);
    ACC_SRC(x2 + ((b * 32 + i) * 32 + j) * 8, 8, 8);
    ACC_SRC(g_R3 + ((b * 32 + i) * 32 + j) * 16, 16, 16);
    ACC_SRC(x1 + (b * 32 + j) * 8, 32, 8);
    ACC_SRC(x2 + ((b * 32 + j) * 32 + i) * 8, 40, 8);
    ACC_SRC(g_R3 + ((b * 32 + j) * 32 + i) * 16, 48, 16);
    #undef ACC_SRC

    float* dst = out2 + (size_t)pos * 16 + o0;
    #pragma unroll
    for (int o = 0; o < 8; o++) dst[o] = sigm(acc[o]);
}

// ---------------------------------------------------------------------------
// Tail B: out1 (blocks 0..15, one CTA per b) + out0 (block 16).
// ---------------------------------------------------------------------------
__global__ void __launch_bounds__(256) k_tail01(
    const float* __restrict__ x0, const float* __restrict__ x1,
    const float* __restrict__ x2,
    const float* __restrict__ W0, const float* __restrict__ b0,
    const float* __restrict__ W1, const float* __restrict__ b1,
    float* __restrict__ out0, float* __restrict__ out1)
{
    int blk = blockIdx.x, tid = threadIdx.x;
    if (blk < 16) {
        int b = blk;
        __shared__ float sMax[32 * 8];
        __shared__ float sMin[32 * 8];
        __shared__ __align__(16) float sW1[32 * 16];
        __shared__ float sX0[8];

        for (int idx = tid; idx < 512; idx += 256) sW1[idx] = W1[idx];
        if (tid < 8) sX0[tid] = x0[b * 8 + tid];
        {
            int i = tid >> 3, c = tid & 7;
            const float* p = x2 + ((b * 32 + i) * 32) * 8 + c;
            float vmax = -INFINITY, vmin = INFINITY;
            #pragma unroll 8
            for (int a = 0; a < 32; a++) {
                float v = p[a * 8];
                float vm = (a == i) ? 0.0f : v;
                float vn = (a == i) ? 1.0f : v;
                vmax = fmaxf(vmax, vm);
                vmin = fminf(vmin, vn);
            }
            sMax[tid] = vmax;
            sMin[tid] = vmin;
        }
        __syncthreads();

        #pragma unroll
        for (int it = 0; it < 2; it++) {
            int item = tid * 2 + it;
            int i = item >> 4, o = item & 15;
            float acc = b1[o];
            const float* x1i = x1 + (b * 32 + i) * 8;
            #pragma unroll
            for (int c = 0; c < 8; c++) {
                acc += sX0[c] * sW1[c * 16 + o];
                acc += x1i[c] * sW1[(8 + c) * 16 + o];
                acc += sMax[i * 8 + c] * sW1[(16 + c) * 16 + o];
                acc += sMin[i * 8 + c] * sW1[(24 + c) * 16 + o];
            }
            out1[(size_t)(b * 32 + i) * 16 + o] = sigm(acc);
        }
    } else {
        int b = tid >> 4, o = tid & 15;
        float acc = b0[o];
        const float* x0b = x0 + b * 8;
        #pragma unroll
        for (int c = 0; c < 8; c++) acc += x0b[c] * W0[c * 16 + o];
        #pragma unroll
        for (int c = 0; c < 8; c++) {
            float vmax = -INFINITY, vmin = INFINITY;
            for (int n = 0; n < 32; n++) {
                float v = x1[(b * 32 + n) * 8 + c];
                vmax = fmaxf(vmax, v);
                vmin = fminf(vmin, v);
            }
            acc += vmax * W0[(8 + c) * 16 + o];
            acc += vmin * W0[(16 + c) * 16 + o];
        }
        out0[b * 16 + o] = sigm(acc);
    }
}

// ---------------------------------------------------------------------------
extern "C" void kernel_launch(void* const* d_in, const int* in_sizes, int n_in,
                              void* d_out, int out_size)
{
    const float* x0 = (const float*)d_in[0];
    const float* x1 = (const float*)d_in[1];
    const float* x2 = (const float*)d_in[2];
    const float* x3 = (const float*)d_in[3];
    const float* W0 = (const float*)d_in[4];
    const float* b0 = (const float*)d_in[5];
    const float* W1 = (const float*)d_in[6];
    const float* b1 = (const float*)d_in[7];
    const float* W2 = (const float*)d_in[8];
    const float* b2 = (const float*)d_in[9];
    const float* W3 = (const float*)d_in[10];
    const float* b3 = (const float*)d_in[11];

    float* out = (float*)d_out;
    float* out0 = out;                 // [16,16]            =     256
    float* out1 = out + 256;           // [16,32,16]         =    8192
    float* out2 = out + 8448;          // [16,32,32,16]      =  262144
    float* out3 = out + 270592;        // [16,32,32,32,16]   = 8388608

    const int smem_bytes = SM_FLOATS * 4;  // 175616
    cudaFuncSetAttribute(k_main, cudaFuncAttributeMaxDynamicSharedMemorySize, smem_bytes);

    // k_main FIRST (3 launches total -> ncu -s5 lands on k_main)
    k_main<<<512, 512, smem_bytes>>>(x2, x3, W3, b3, out3);
    k_tail2<<<128, 256>>>(x1, x2, W2, b2, out2);
    k_tail01<<<17, 256>>>(x0, x1, x2, W0, b0, W1, b1, out0, out1);
}